// round 7
// baseline (speedup 1.0000x reference)
#include <cuda_runtime.h>
#include <math.h>

#define F_BINS   4096
#define W_HALF   128
#define TAPS     (2*W_HALF)            // 256
#define NBUF_LEN (F_BINS + 2*W_HALF)   // 4352
#define NCH      48
#define NCT      96
#define NSLICE   4
#define NCTA     (NCT*NSLICE)          // 384
#define HW_IN    (512*512)
#define BROWS    16
#define HROWS    (2*BROWS + 2)         // 34
#define USTEP    0.0732421875f         // 300/4096

// scratch (static device globals -- zero-initialized at module load; winner re-zeroes each launch)
__device__ __align__(16) float g_T[NCT * 257];
__device__ int g_done_all;

#define K1_SMEM (F_BINS*4 + HROWS*256*4)   // 16384 + 34816 = 51200

__global__ void __launch_bounds__(512) k_all(const float* __restrict__ pred,
                                             const float* __restrict__ tgt,
                                             float* __restrict__ out) {
    extern __shared__ unsigned char smraw[];
    unsigned int* sh_hist = reinterpret_cast<unsigned int*>(smraw);          // [4096]
    float* sh_h = reinterpret_cast<float*>(smraw + F_BINS*4);                // [34][256] phase A
    __shared__ float csuf[257];
    __shared__ float chunk[256];
    __shared__ int s_ticket;
    __shared__ float s_red[16];

    const int ct    = blockIdx.x;   // 0..95
    const int slice = blockIdx.y;   // 0..3
    const int tid   = threadIdx.x;
    const int warp  = tid >> 5, lane = tid & 31;
    const unsigned FULL = 0xffffffffu;

    const int r0 = slice * 64;
    const int r1 = r0 + 64;

    const float* src = (ct < NCH) ? (pred + (size_t)ct * HW_IN)
                                  : (tgt  + (size_t)(ct - NCH) * HW_IN);

    // per-thread sigmoid table: 2 float4, tap t = 4*(q*32+lane)+s, u = USTEP*(t-127.5)
    float4 tb[2];
    #pragma unroll
    for (int q = 0; q < 2; q++) {
        float j0 = (float)(128*q + 4*lane);
        tb[q].x = 1.f / (1.f + expf(-USTEP * (j0 + 0.f - 127.5f)));
        tb[q].y = 1.f / (1.f + expf(-USTEP * (j0 + 1.f - 127.5f)));
        tb[q].z = 1.f / (1.f + expf(-USTEP * (j0 + 2.f - 127.5f)));
        tb[q].w = 1.f / (1.f + expf(-USTEP * (j0 + 3.f - 127.5f)));
    }

    // ================= Phase A: resize + private slice histogram =================
    for (int i = tid; i < F_BINS; i += 512) sh_hist[i] = 0u;
    __syncthreads();

    for (int oyb = r0; oyb < r1; oyb += BROWS) {
        for (int lr = warp; lr < HROWS; lr += 16) {
            int iy = 2*oyb - 1 + lr;
            iy = iy < 0 ? 0 : (iy > 511 ? 511 : iy);
            const float4* row4 = reinterpret_cast<const float4*>(src + (size_t)iy * 512);
            float4 v0 = row4[lane];
            float4 v1 = row4[32 + lane];
            float4 v2 = row4[64 + lane];
            float4 v3 = row4[96 + lane];
            float cl1 = __shfl_sync(FULL, v0.w, 31);
            float cl2 = __shfl_sync(FULL, v1.w, 31);
            float cl3 = __shfl_sync(FULL, v2.w, 31);
            float cr0 = __shfl_sync(FULL, v1.x, 0);
            float cr1 = __shfl_sync(FULL, v2.x, 0);
            float cr2 = __shfl_sync(FULL, v3.x, 0);
            float carryL[4] = {0.f, cl1, cl2, cl3};
            float carryR[4] = {cr0, cr1, cr2, 0.f};
            float4 vv[4] = {v0, v1, v2, v3};
            float2* hd = reinterpret_cast<float2*>(sh_h + lr*256);
            #pragma unroll
            for (int c = 0; c < 4; c++) {
                float4 v = vv[c];
                float left  = __shfl_up_sync(FULL, v.w, 1);
                if (lane == 0)  left  = carryL[c];
                float right = __shfl_down_sync(FULL, v.x, 1);
                if (lane == 31) right = carryR[c];
                float ha, hb;
                if (c == 0 && lane == 0)
                    ha = (3.f*v.x + 3.f*v.y + v.z) * (1.f/7.f);
                else
                    ha = (left + 3.f*v.x + 3.f*v.y + v.z) * 0.125f;
                if (c == 3 && lane == 31)
                    hb = (v.y + 3.f*v.z + 3.f*v.w) * (1.f/7.f);
                else
                    hb = (v.y + 3.f*v.z + 3.f*v.w + right) * 0.125f;
                hd[c*32 + lane] = make_float2(ha, hb);
            }
        }
        __syncthreads();

        for (int p = tid; p < BROWS*256; p += 512) {
            int oyl = p >> 8;
            int ox  = p & 255;
            int oy  = oyb + oyl;
            const float* hp = sh_h + (2*oyl)*256 + ox;
            float a0 = hp[0], a1 = hp[256], a2 = hp[512], a3 = hp[768];
            float inv = (oy == 0 || oy == 255) ? (1.f/7.f) : 0.125f;
            float w0 = (oy == 0)   ? 0.f : inv;
            float w3 = (oy == 255) ? 0.f : inv;
            float val = w0*a0 + 3.f*inv*(a1 + a2) + w3*a3;
            int bin = (int)(val * (float)F_BINS);
            bin = bin < 0 ? 0 : (bin > F_BINS-1 ? F_BINS-1 : bin);
            atomicAdd(&sh_hist[bin], 1u);
        }
        __syncthreads();
    }

    // ================= Phase B (per-CTA): partial T(m) from OWN slice hist =================
    float* nbuf = reinterpret_cast<float*>(smraw + F_BINS*4);   // [4352], aliases sh_h

    if (tid < W_HALF) {
        nbuf[tid] = 0.f;
        nbuf[W_HALF + F_BINS + tid] = 0.f;
    }
    __syncthreads();
    for (int k = tid; k < F_BINS; k += 512)
        nbuf[W_HALF + k] = (float)sh_hist[k];
    __syncthreads();

    // 16-bin chunk sums (one per coarse bin)
    if (tid < 256) {
        const float4* p4 = reinterpret_cast<const float4*>(nbuf + W_HALF) + tid*4;
        float4 v0 = p4[0], v1 = p4[1], v2 = p4[2], v3 = p4[3];
        chunk[tid] = (v0.x+v0.y+v0.z+v0.w) + (v1.x+v1.y+v1.z+v1.w)
                   + (v2.x+v2.y+v2.z+v2.w) + (v3.x+v3.y+v3.z+v3.w);
    }
    __syncthreads();
    if (tid < 32) {      // suffix scan of 256 chunks
        float loc[8];
        float run = 0.f;
        #pragma unroll
        for (int i = 7; i >= 0; i--) { run += chunk[tid*8 + i]; loc[i] = run; }
        float t_l = run, suf = run;
        #pragma unroll
        for (int off = 1; off < 32; off <<= 1) {
            float v = __shfl_down_sync(FULL, suf, off);
            if (tid + off < 32) suf += v;
        }
        float above = suf - t_l;
        #pragma unroll
        for (int i = 0; i < 8; i++) csuf[tid*8 + i] = loc[i] + above;
        if (tid == 0) csuf[256] = 0.f;
    }
    __syncthreads();

    const float4* nb4 = reinterpret_cast<const float4*>(nbuf);
    for (int m = warp; m <= 256; m += 16) {
        const float4* base = nb4 + m*4;      // window [16m-128, 16m+128) at padded offset 16m
        float4 x0 = base[lane];
        float4 x1 = base[32 + lane];
        float acc = x0.x*tb[0].x + x0.y*tb[0].y + x0.z*tb[0].z + x0.w*tb[0].w
                  + x1.x*tb[1].x + x1.y*tb[1].y + x1.z*tb[1].z + x1.w*tb[1].w;
        #pragma unroll
        for (int off = 16; off; off >>= 1)
            acc += __shfl_down_sync(FULL, acc, off);
        if (lane == 0) {
            int cc = m + 8;                  // counts for fine bins >= 16m+128
            float S = (cc < 256) ? csuf[cc] : 0.f;
            atomicAdd(&g_T[ct*257 + m], S + acc);
        }
    }

    // ================= Ticket: last CTA of the whole grid does the reduction =================
    __syncthreads();
    __threadfence();
    if (tid == 0) s_ticket = atomicAdd(&g_done_all, 1);
    __syncthreads();
    if (s_ticket != NCTA - 1) return;
    if (tid == 0) atomicExch(&g_done_all, 0);   // self-reset for next replay

    // ================= Phase C: CDF L1 reduction =================
    float s = 0.f;
    for (int e = tid; e < NCH*256; e += 512) {
        int p  = e >> 8;
        int bb = e & 255;
        const float* Tp = g_T + p*257;
        const float* Tt = g_T + (NCH + p)*257;
        float p0 = __ldcg(&Tp[0]), t0 = __ldcg(&Tt[0]);
        float pe = __ldcg(&Tp[256]), te = __ldcg(&Tt[256]);
        float invp = 1.f / (p0 - pe);
        float invt = 1.f / (t0 - te);
        float cp  = (p0 - __ldcg(&Tp[bb+1])) * invp;
        float ctv = (t0 - __ldcg(&Tt[bb+1])) * invt;
        s += fabsf(cp - ctv);
    }
    #pragma unroll
    for (int off = 16; off; off >>= 1) s += __shfl_down_sync(FULL, s, off);
    if (lane == 0) s_red[warp] = s;
    __syncthreads();
    if (tid < 32) {
        float v = (tid < 16) ? s_red[tid] : 0.f;
        #pragma unroll
        for (int off = 16; off; off >>= 1) v += __shfl_down_sync(FULL, v, off);
        if (tid == 0) out[0] = v * (1.0f / (48.0f * 256.0f));
    }
    __syncthreads();
    // zero g_T for the next graph replay (values already consumed above)
    for (int i = tid; i < NCT*257; i += 512) g_T[i] = 0.f;
}

extern "C" void kernel_launch(void* const* d_in, const int* in_sizes, int n_in,
                              void* d_out, int out_size) {
    const float* pred = (const float*)d_in[0];
    const float* tgt  = (const float*)d_in[1];
    float* out = (float*)d_out;

    cudaFuncSetAttribute(k_all, cudaFuncAttributeMaxDynamicSharedMemorySize, K1_SMEM);
    k_all<<<dim3(NCT, NSLICE), 512, K1_SMEM>>>(pred, tgt, out);
}

// round 8
// speedup vs baseline: 1.2088x; 1.2088x over previous
#include <cuda_runtime.h>
#include <math.h>

#define F_BINS   4096
#define W_HALF   128
#define TAPS     (2*W_HALF)            // 256
#define NBUF_LEN (F_BINS + 2*W_HALF)   // 4352
#define NCH      48
#define NCT      96
#define NSLICE   4
#define NCTA     (NCT*NSLICE)          // 384
#define HW_IN    (512*512)
#define BROWS    16
#define HROWS    (2*BROWS + 2)         // 34
#define USTEP    0.0732421875f         // 300/4096

// scratch (static device globals -- zero-initialized at module load; winner re-zeroes each launch)
__device__ __align__(16) float g_T[NCT * 257];
__device__ int g_done_all;

#define K1_SMEM (F_BINS*4 + HROWS*256*4)   // 16384 + 34816 = 51200

__global__ void __launch_bounds__(512, 3) k_all(const float* __restrict__ pred,
                                                const float* __restrict__ tgt,
                                                float* __restrict__ out) {
    extern __shared__ unsigned char smraw[];
    unsigned int* sh_hist = reinterpret_cast<unsigned int*>(smraw);          // [4096]
    float* sh_h = reinterpret_cast<float*>(smraw + F_BINS*4);                // [34][256] phase A
    __shared__ __align__(16) float tab[TAPS];                                // sigmoid taps
    __shared__ float csuf[257];
    __shared__ float chunk[256];
    __shared__ int s_ticket;
    __shared__ float s_red[16];

    const int ct    = blockIdx.x;   // 0..95
    const int slice = blockIdx.y;   // 0..3
    const int tid   = threadIdx.x;
    const int warp  = tid >> 5, lane = tid & 31;
    const unsigned FULL = 0xffffffffu;

    const int r0 = slice * 64;
    const int r1 = r0 + 64;

    const float* src = (ct < NCH) ? (pred + (size_t)ct * HW_IN)
                                  : (tgt  + (size_t)(ct - NCH) * HW_IN);

    // init sigmoid table (once, cheap) + zero private histogram
    if (tid < TAPS)
        tab[tid] = 1.f / (1.f + expf(-USTEP * ((float)tid - 127.5f)));
    for (int i = tid; i < F_BINS; i += 512) sh_hist[i] = 0u;
    __syncthreads();

    // ================= Phase A: resize + private slice histogram =================
    for (int oyb = r0; oyb < r1; oyb += BROWS) {
        for (int lr = warp; lr < HROWS; lr += 16) {
            int iy = 2*oyb - 1 + lr;
            iy = iy < 0 ? 0 : (iy > 511 ? 511 : iy);
            const float4* row4 = reinterpret_cast<const float4*>(src + (size_t)iy * 512);
            float4 v0 = row4[lane];
            float4 v1 = row4[32 + lane];
            float4 v2 = row4[64 + lane];
            float4 v3 = row4[96 + lane];
            float cl1 = __shfl_sync(FULL, v0.w, 31);
            float cl2 = __shfl_sync(FULL, v1.w, 31);
            float cl3 = __shfl_sync(FULL, v2.w, 31);
            float cr0 = __shfl_sync(FULL, v1.x, 0);
            float cr1 = __shfl_sync(FULL, v2.x, 0);
            float cr2 = __shfl_sync(FULL, v3.x, 0);
            float carryL[4] = {0.f, cl1, cl2, cl3};
            float carryR[4] = {cr0, cr1, cr2, 0.f};
            float4 vv[4] = {v0, v1, v2, v3};
            float2* hd = reinterpret_cast<float2*>(sh_h + lr*256);
            #pragma unroll
            for (int c = 0; c < 4; c++) {
                float4 v = vv[c];
                float left  = __shfl_up_sync(FULL, v.w, 1);
                if (lane == 0)  left  = carryL[c];
                float right = __shfl_down_sync(FULL, v.x, 1);
                if (lane == 31) right = carryR[c];
                float ha, hb;
                if (c == 0 && lane == 0)
                    ha = (3.f*v.x + 3.f*v.y + v.z) * (1.f/7.f);
                else
                    ha = (left + 3.f*v.x + 3.f*v.y + v.z) * 0.125f;
                if (c == 3 && lane == 31)
                    hb = (v.y + 3.f*v.z + 3.f*v.w) * (1.f/7.f);
                else
                    hb = (v.y + 3.f*v.z + 3.f*v.w + right) * 0.125f;
                hd[c*32 + lane] = make_float2(ha, hb);
            }
        }
        __syncthreads();

        for (int p = tid; p < BROWS*256; p += 512) {
            int oyl = p >> 8;
            int ox  = p & 255;
            int oy  = oyb + oyl;
            const float* hp = sh_h + (2*oyl)*256 + ox;
            float a0 = hp[0], a1 = hp[256], a2 = hp[512], a3 = hp[768];
            float inv = (oy == 0 || oy == 255) ? (1.f/7.f) : 0.125f;
            float w0 = (oy == 0)   ? 0.f : inv;
            float w3 = (oy == 255) ? 0.f : inv;
            float val = w0*a0 + 3.f*inv*(a1 + a2) + w3*a3;
            int bin = (int)(val * (float)F_BINS);
            bin = bin < 0 ? 0 : (bin > F_BINS-1 ? F_BINS-1 : bin);
            atomicAdd(&sh_hist[bin], 1u);
        }
        __syncthreads();
    }

    // ================= Phase B (per-CTA): partial T(m) from OWN slice hist =================
    float* nbuf = reinterpret_cast<float*>(smraw + F_BINS*4);   // [4352], aliases sh_h

    if (tid < W_HALF) {
        nbuf[tid] = 0.f;
        nbuf[W_HALF + F_BINS + tid] = 0.f;
    }
    __syncthreads();
    for (int k = tid; k < F_BINS; k += 512)
        nbuf[W_HALF + k] = (float)sh_hist[k];
    __syncthreads();

    // 16-bin chunk sums (one per coarse bin)
    if (tid < 256) {
        const float4* p4 = reinterpret_cast<const float4*>(nbuf + W_HALF) + tid*4;
        float4 v0 = p4[0], v1 = p4[1], v2 = p4[2], v3 = p4[3];
        chunk[tid] = (v0.x+v0.y+v0.z+v0.w) + (v1.x+v1.y+v1.z+v1.w)
                   + (v2.x+v2.y+v2.z+v2.w) + (v3.x+v3.y+v3.z+v3.w);
    }
    __syncthreads();
    if (tid < 32) {      // suffix scan of 256 chunks
        float loc[8];
        float run = 0.f;
        #pragma unroll
        for (int i = 7; i >= 0; i--) { run += chunk[tid*8 + i]; loc[i] = run; }
        float t_l = run, suf = run;
        #pragma unroll
        for (int off = 1; off < 32; off <<= 1) {
            float v = __shfl_down_sync(FULL, suf, off);
            if (tid + off < 32) suf += v;
        }
        float above = suf - t_l;
        #pragma unroll
        for (int i = 0; i < 8; i++) csuf[tid*8 + i] = loc[i] + above;
        if (tid == 0) csuf[256] = 0.f;
    }
    __syncthreads();

    const float4* nb4 = reinterpret_cast<const float4*>(nbuf);
    const float4* tb4 = reinterpret_cast<const float4*>(tab);
    for (int m = warp; m <= 256; m += 16) {
        const float4* base = nb4 + m*4;      // window [16m-128, 16m+128) at padded offset 16m
        float4 x0 = base[lane];
        float4 x1 = base[32 + lane];
        float4 t0 = tb4[lane];
        float4 t1 = tb4[32 + lane];
        float acc = x0.x*t0.x + x0.y*t0.y + x0.z*t0.z + x0.w*t0.w
                  + x1.x*t1.x + x1.y*t1.y + x1.z*t1.z + x1.w*t1.w;
        #pragma unroll
        for (int off = 16; off; off >>= 1)
            acc += __shfl_down_sync(FULL, acc, off);
        if (lane == 0) {
            int cc = m + 8;                  // counts for fine bins >= 16m+128
            float S = (cc < 256) ? csuf[cc] : 0.f;
            atomicAdd(&g_T[ct*257 + m], S + acc);
        }
    }

    // ================= Ticket: last CTA of the whole grid does the reduction =================
    __syncthreads();
    __threadfence();
    if (tid == 0) s_ticket = atomicAdd(&g_done_all, 1);
    __syncthreads();
    if (s_ticket != NCTA - 1) return;
    if (tid == 0) atomicExch(&g_done_all, 0);   // self-reset for next replay

    // ================= Phase C: CDF L1 reduction =================
    float s = 0.f;
    for (int e = tid; e < NCH*256; e += 512) {
        int p  = e >> 8;
        int bb = e & 255;
        const float* Tp = g_T + p*257;
        const float* Tt = g_T + (NCH + p)*257;
        float p0 = __ldcg(&Tp[0]), t0 = __ldcg(&Tt[0]);
        float pe = __ldcg(&Tp[256]), te = __ldcg(&Tt[256]);
        float invp = 1.f / (p0 - pe);
        float invt = 1.f / (t0 - te);
        float cp  = (p0 - __ldcg(&Tp[bb+1])) * invp;
        float ctv = (t0 - __ldcg(&Tt[bb+1])) * invt;
        s += fabsf(cp - ctv);
    }
    #pragma unroll
    for (int off = 16; off; off >>= 1) s += __shfl_down_sync(FULL, s, off);
    if (lane == 0) s_red[warp] = s;
    __syncthreads();
    if (tid < 32) {
        float v = (tid < 16) ? s_red[tid] : 0.f;
        #pragma unroll
        for (int off = 16; off; off >>= 1) v += __shfl_down_sync(FULL, v, off);
        if (tid == 0) out[0] = v * (1.0f / (48.0f * 256.0f));
    }
    __syncthreads();
    // zero g_T for the next graph replay (values already consumed above)
    for (int i = tid; i < NCT*257; i += 512) g_T[i] = 0.f;
}

extern "C" void kernel_launch(void* const* d_in, const int* in_sizes, int n_in,
                              void* d_out, int out_size) {
    const float* pred = (const float*)d_in[0];
    const float* tgt  = (const float*)d_in[1];
    float* out = (float*)d_out;

    cudaFuncSetAttribute(k_all, cudaFuncAttributeMaxDynamicSharedMemorySize, K1_SMEM);
    k_all<<<dim3(NCT, NSLICE), 512, K1_SMEM>>>(pred, tgt, out);
}

// round 9
// speedup vs baseline: 1.2678x; 1.0488x over previous
#include <cuda_runtime.h>
#include <math.h>

#define F_BINS   4096
#define W_HALF   128
#define TAPS     (2*W_HALF)            // 256
#define NBUF_LEN (F_BINS + 2*W_HALF)   // 4352
#define NCH      48
#define NCT      96
#define NSLICE   4
#define NCTA     (NCT*NSLICE)          // 384
#define HW_IN    (512*512)
#define BROWS    16
#define HROWS    (2*BROWS + 2)         // 34
#define USTEP    0.0732421875f         // 300/4096

// scratch (static device globals -- zero-initialized at module load; winner re-zeroes each launch)
__device__ __align__(16) float g_T[NCT * 257];
__device__ int g_done_all;

#define K1_SMEM (F_BINS*4 + HROWS*256*4)   // 16384 + 34816 = 51200

__global__ void __launch_bounds__(512, 3) k_all(const float* __restrict__ pred,
                                                const float* __restrict__ tgt,
                                                float* __restrict__ out) {
    extern __shared__ unsigned char smraw[];
    unsigned int* sh_hist = reinterpret_cast<unsigned int*>(smraw);          // [4096]
    float* sh_h = reinterpret_cast<float*>(smraw + F_BINS*4);                // [34][256] phase A
    __shared__ __align__(16) float tab[TAPS];                                // sigmoid taps
    __shared__ float csuf[257];
    __shared__ float chunk[256];
    __shared__ int s_ticket;
    __shared__ float s_red[16];

    const int ct    = blockIdx.x;   // 0..95
    const int slice = blockIdx.y;   // 0..3
    const int tid   = threadIdx.x;
    const int warp  = tid >> 5, lane = tid & 31;
    const unsigned FULL = 0xffffffffu;

    const int r0 = slice * 64;
    const int r1 = r0 + 64;

    const float* src = (ct < NCH) ? (pred + (size_t)ct * HW_IN)
                                  : (tgt  + (size_t)(ct - NCH) * HW_IN);

    // init sigmoid table (once, cheap) + zero private histogram
    if (tid < TAPS)
        tab[tid] = 1.f / (1.f + expf(-USTEP * ((float)tid - 127.5f)));
    for (int i = tid; i < F_BINS; i += 512) sh_hist[i] = 0u;
    __syncthreads();

    // ================= Phase A: resize + private slice histogram =================
    for (int oyb = r0; oyb < r1; oyb += BROWS) {
        for (int lr = warp; lr < HROWS; lr += 16) {
            int iy = 2*oyb - 1 + lr;
            iy = iy < 0 ? 0 : (iy > 511 ? 511 : iy);
            const float4* row4 = reinterpret_cast<const float4*>(src + (size_t)iy * 512);
            float4 v0 = row4[lane];
            float4 v1 = row4[32 + lane];
            float4 v2 = row4[64 + lane];
            float4 v3 = row4[96 + lane];
            float cl1 = __shfl_sync(FULL, v0.w, 31);
            float cl2 = __shfl_sync(FULL, v1.w, 31);
            float cl3 = __shfl_sync(FULL, v2.w, 31);
            float cr0 = __shfl_sync(FULL, v1.x, 0);
            float cr1 = __shfl_sync(FULL, v2.x, 0);
            float cr2 = __shfl_sync(FULL, v3.x, 0);
            float carryL[4] = {0.f, cl1, cl2, cl3};
            float carryR[4] = {cr0, cr1, cr2, 0.f};
            float4 vv[4] = {v0, v1, v2, v3};
            float2* hd = reinterpret_cast<float2*>(sh_h + lr*256);
            #pragma unroll
            for (int c = 0; c < 4; c++) {
                float4 v = vv[c];
                float left  = __shfl_up_sync(FULL, v.w, 1);
                if (lane == 0)  left  = carryL[c];
                float right = __shfl_down_sync(FULL, v.x, 1);
                if (lane == 31) right = carryR[c];
                float ha, hb;
                if (c == 0 && lane == 0)
                    ha = (3.f*v.x + 3.f*v.y + v.z) * (1.f/7.f);
                else
                    ha = (left + 3.f*v.x + 3.f*v.y + v.z) * 0.125f;
                if (c == 3 && lane == 31)
                    hb = (v.y + 3.f*v.z + 3.f*v.w) * (1.f/7.f);
                else
                    hb = (v.y + 3.f*v.z + 3.f*v.w + right) * 0.125f;
                hd[c*32 + lane] = make_float2(ha, hb);
            }
        }
        __syncthreads();

        for (int p = tid; p < BROWS*256; p += 512) {
            int oyl = p >> 8;
            int ox  = p & 255;
            int oy  = oyb + oyl;
            const float* hp = sh_h + (2*oyl)*256 + ox;
            float a0 = hp[0], a1 = hp[256], a2 = hp[512], a3 = hp[768];
            float inv = (oy == 0 || oy == 255) ? (1.f/7.f) : 0.125f;
            float w0 = (oy == 0)   ? 0.f : inv;
            float w3 = (oy == 255) ? 0.f : inv;
            float val = w0*a0 + 3.f*inv*(a1 + a2) + w3*a3;
            int bin = (int)(val * (float)F_BINS);
            bin = bin < 0 ? 0 : (bin > F_BINS-1 ? F_BINS-1 : bin);
            atomicAdd(&sh_hist[bin], 1u);
        }
        __syncthreads();
    }

    // ================= Phase B (per-CTA): partial T(m) from OWN slice hist =================
    float* nbuf = reinterpret_cast<float*>(smraw + F_BINS*4);   // [4352], aliases sh_h

    if (tid < W_HALF) {
        nbuf[tid] = 0.f;
        nbuf[W_HALF + F_BINS + tid] = 0.f;
    }
    __syncthreads();
    for (int k = tid; k < F_BINS; k += 512)
        nbuf[W_HALF + k] = (float)sh_hist[k];
    __syncthreads();

    // 16-bin chunk sums (one per coarse bin)
    if (tid < 256) {
        const float4* p4 = reinterpret_cast<const float4*>(nbuf + W_HALF) + tid*4;
        float4 v0 = p4[0], v1 = p4[1], v2 = p4[2], v3 = p4[3];
        chunk[tid] = (v0.x+v0.y+v0.z+v0.w) + (v1.x+v1.y+v1.z+v1.w)
                   + (v2.x+v2.y+v2.z+v2.w) + (v3.x+v3.y+v3.z+v3.w);
    }
    __syncthreads();
    if (tid < 32) {      // suffix scan of 256 chunks
        float loc[8];
        float run = 0.f;
        #pragma unroll
        for (int i = 7; i >= 0; i--) { run += chunk[tid*8 + i]; loc[i] = run; }
        float t_l = run, suf = run;
        #pragma unroll
        for (int off = 1; off < 32; off <<= 1) {
            float v = __shfl_down_sync(FULL, suf, off);
            if (tid + off < 32) suf += v;
        }
        float above = suf - t_l;
        #pragma unroll
        for (int i = 0; i < 8; i++) csuf[tid*8 + i] = loc[i] + above;
        if (tid == 0) csuf[256] = 0.f;
    }
    __syncthreads();

    // σ taps into registers -- B-scope only (loaded after phase A's reg peak)
    const float4* tb4 = reinterpret_cast<const float4*>(tab);
    const float4  tr0 = tb4[lane];
    const float4  tr1 = tb4[32 + lane];

    const float4* nb4 = reinterpret_cast<const float4*>(nbuf);
    float* gT = g_T + ct*257;
    int m = warp;
    for (; m + 16 <= 256; m += 32) {
        const float4* baseA = nb4 + m*4;          // window [16m-128,16m+128)
        const float4* baseB = nb4 + (m+16)*4;
        float4 a0 = baseA[lane];
        float4 a1 = baseA[32 + lane];
        float4 b0 = baseB[lane];
        float4 b1 = baseB[32 + lane];
        float accA = a0.x*tr0.x + a0.y*tr0.y + a0.z*tr0.z + a0.w*tr0.w
                   + a1.x*tr1.x + a1.y*tr1.y + a1.z*tr1.z + a1.w*tr1.w;
        float accB = b0.x*tr0.x + b0.y*tr0.y + b0.z*tr0.z + b0.w*tr0.w
                   + b1.x*tr1.x + b1.y*tr1.y + b1.z*tr1.z + b1.w*tr1.w;
        #pragma unroll
        for (int off = 16; off; off >>= 1) {
            accA += __shfl_down_sync(FULL, accA, off);
            accB += __shfl_down_sync(FULL, accB, off);
        }
        if (lane == 0) {
            int ca = m + 8, cb = m + 24;
            float SA = (ca < 256) ? csuf[ca] : 0.f;
            float SB = (cb < 256) ? csuf[cb] : 0.f;
            atomicAdd(&gT[m],      SA + accA);
            atomicAdd(&gT[m + 16], SB + accB);
        }
    }
    if (m <= 256) {                                // warp 0 tail: m = 256
        const float4* base = nb4 + m*4;
        float4 a0 = base[lane];
        float4 a1 = base[32 + lane];
        float acc = a0.x*tr0.x + a0.y*tr0.y + a0.z*tr0.z + a0.w*tr0.w
                  + a1.x*tr1.x + a1.y*tr1.y + a1.z*tr1.z + a1.w*tr1.w;
        #pragma unroll
        for (int off = 16; off; off >>= 1)
            acc += __shfl_down_sync(FULL, acc, off);
        if (lane == 0) atomicAdd(&gT[m], acc);     // suffix is 0 for m=256
    }

    // ================= Ticket: last CTA of the whole grid does the reduction =================
    __syncthreads();
    if (tid == 0) {                 // barrier ordered all CTA writes; one fence suffices
        __threadfence();
        s_ticket = atomicAdd(&g_done_all, 1);
    }
    __syncthreads();
    if (s_ticket != NCTA - 1) return;
    if (tid == 0) atomicExch(&g_done_all, 0);   // self-reset for next replay

    // ================= Phase C: CDF L1 reduction =================
    float s = 0.f;
    for (int e = tid; e < NCH*256; e += 512) {
        int p  = e >> 8;
        int bb = e & 255;
        const float* Tp = g_T + p*257;
        const float* Tt = g_T + (NCH + p)*257;
        float p0 = __ldcg(&Tp[0]), t0 = __ldcg(&Tt[0]);
        float pe = __ldcg(&Tp[256]), te = __ldcg(&Tt[256]);
        float invp = 1.f / (p0 - pe);
        float invt = 1.f / (t0 - te);
        float cp  = (p0 - __ldcg(&Tp[bb+1])) * invp;
        float ctv = (t0 - __ldcg(&Tt[bb+1])) * invt;
        s += fabsf(cp - ctv);
    }
    #pragma unroll
    for (int off = 16; off; off >>= 1) s += __shfl_down_sync(FULL, s, off);
    if (lane == 0) s_red[warp] = s;
    __syncthreads();
    if (tid < 32) {
        float v = (tid < 16) ? s_red[tid] : 0.f;
        #pragma unroll
        for (int off = 16; off; off >>= 1) v += __shfl_down_sync(FULL, v, off);
        if (tid == 0) out[0] = v * (1.0f / (48.0f * 256.0f));
    }
    __syncthreads();
    // zero g_T for the next graph replay (values already consumed above)
    for (int i = tid; i < NCT*257; i += 512) g_T[i] = 0.f;
}

extern "C" void kernel_launch(void* const* d_in, const int* in_sizes, int n_in,
                              void* d_out, int out_size) {
    const float* pred = (const float*)d_in[0];
    const float* tgt  = (const float*)d_in[1];
    float* out = (float*)d_out;

    cudaFuncSetAttribute(k_all, cudaFuncAttributeMaxDynamicSharedMemorySize, K1_SMEM);
    k_all<<<dim3(NCT, NSLICE), 512, K1_SMEM>>>(pred, tgt, out);
}

// round 10
// speedup vs baseline: 1.3651x; 1.0767x over previous
#include <cuda_runtime.h>
#include <math.h>

#define F_BINS   2048
#define W_HALF   64
#define TAPS     (2*W_HALF)            // 128
#define NBUF_LEN (F_BINS + 2*W_HALF)   // 2176
#define NCH      48
#define NCT      96
#define NSLICE   4
#define NCTA     (NCT*NSLICE)          // 384
#define HW_IN    (512*512)
#define BROWS    16
#define HROWS    (2*BROWS + 2)         // 34
#define USTEP    0.146484375f          // 300/2048

// scratch (static device globals -- zero-initialized at module load; winner re-zeroes each launch)
__device__ __align__(16) float g_T[NCT * 257];
__device__ int g_done_all;

#define K1_SMEM (F_BINS*4 + HROWS*256*4)   // 8192 + 34816 = 43008

__global__ void __launch_bounds__(512, 3) k_all(const float* __restrict__ pred,
                                                const float* __restrict__ tgt,
                                                float* __restrict__ out) {
    extern __shared__ unsigned char smraw[];
    unsigned int* sh_hist = reinterpret_cast<unsigned int*>(smraw);          // [2048]
    float* sh_h = reinterpret_cast<float*>(smraw + F_BINS*4);                // [34][256] phase A
    __shared__ __align__(16) float tab[TAPS];                                // sigmoid taps
    __shared__ float csuf[257];
    __shared__ float chunk[256];
    __shared__ int s_ticket;
    __shared__ float s_red[16];

    const int ct    = blockIdx.x;   // 0..95
    const int slice = blockIdx.y;   // 0..3
    const int tid   = threadIdx.x;
    const int warp  = tid >> 5, lane = tid & 31;
    const unsigned FULL = 0xffffffffu;

    const int r0 = slice * 64;
    const int r1 = r0 + 64;

    const float* src = (ct < NCH) ? (pred + (size_t)ct * HW_IN)
                                  : (tgt  + (size_t)(ct - NCH) * HW_IN);

    // init sigmoid table (once, cheap) + zero private histogram
    if (tid < TAPS)
        tab[tid] = 1.f / (1.f + expf(-USTEP * ((float)tid - 63.5f)));
    for (int i = tid; i < F_BINS; i += 512) sh_hist[i] = 0u;
    __syncthreads();

    // ================= Phase A: resize + private slice histogram =================
    for (int oyb = r0; oyb < r1; oyb += BROWS) {
        for (int lr = warp; lr < HROWS; lr += 16) {
            int iy = 2*oyb - 1 + lr;
            iy = iy < 0 ? 0 : (iy > 511 ? 511 : iy);
            const float4* row4 = reinterpret_cast<const float4*>(src + (size_t)iy * 512);
            float4 v0 = row4[lane];
            float4 v1 = row4[32 + lane];
            float4 v2 = row4[64 + lane];
            float4 v3 = row4[96 + lane];
            float cl1 = __shfl_sync(FULL, v0.w, 31);
            float cl2 = __shfl_sync(FULL, v1.w, 31);
            float cl3 = __shfl_sync(FULL, v2.w, 31);
            float cr0 = __shfl_sync(FULL, v1.x, 0);
            float cr1 = __shfl_sync(FULL, v2.x, 0);
            float cr2 = __shfl_sync(FULL, v3.x, 0);
            float carryL[4] = {0.f, cl1, cl2, cl3};
            float carryR[4] = {cr0, cr1, cr2, 0.f};
            float4 vv[4] = {v0, v1, v2, v3};
            float2* hd = reinterpret_cast<float2*>(sh_h + lr*256);
            #pragma unroll
            for (int c = 0; c < 4; c++) {
                float4 v = vv[c];
                float left  = __shfl_up_sync(FULL, v.w, 1);
                if (lane == 0)  left  = carryL[c];
                float right = __shfl_down_sync(FULL, v.x, 1);
                if (lane == 31) right = carryR[c];
                float ha, hb;
                if (c == 0 && lane == 0)
                    ha = (3.f*v.x + 3.f*v.y + v.z) * (1.f/7.f);
                else
                    ha = (left + 3.f*v.x + 3.f*v.y + v.z) * 0.125f;
                if (c == 3 && lane == 31)
                    hb = (v.y + 3.f*v.z + 3.f*v.w) * (1.f/7.f);
                else
                    hb = (v.y + 3.f*v.z + 3.f*v.w + right) * 0.125f;
                hd[c*32 + lane] = make_float2(ha, hb);
            }
        }
        __syncthreads();

        for (int p = tid; p < BROWS*256; p += 512) {
            int oyl = p >> 8;
            int ox  = p & 255;
            int oy  = oyb + oyl;
            const float* hp = sh_h + (2*oyl)*256 + ox;
            float a0 = hp[0], a1 = hp[256], a2 = hp[512], a3 = hp[768];
            float inv = (oy == 0 || oy == 255) ? (1.f/7.f) : 0.125f;
            float w0 = (oy == 0)   ? 0.f : inv;
            float w3 = (oy == 255) ? 0.f : inv;
            float val = w0*a0 + 3.f*inv*(a1 + a2) + w3*a3;
            int bin = (int)(val * (float)F_BINS);
            bin = bin < 0 ? 0 : (bin > F_BINS-1 ? F_BINS-1 : bin);
            atomicAdd(&sh_hist[bin], 1u);
        }
        __syncthreads();
    }

    // ================= Phase B (per-CTA): partial T(m) from OWN slice hist =================
    float* nbuf = reinterpret_cast<float*>(smraw + F_BINS*4);   // [2176], aliases sh_h

    if (tid < W_HALF) {
        nbuf[tid] = 0.f;
        nbuf[W_HALF + F_BINS + tid] = 0.f;
    }
    __syncthreads();
    for (int k = tid; k < F_BINS; k += 512)
        nbuf[W_HALF + k] = (float)sh_hist[k];
    __syncthreads();

    // 8-bin chunk sums (one per coarse bin): 256 chunks
    if (tid < 256) {
        const float4* p4 = reinterpret_cast<const float4*>(nbuf + W_HALF) + tid*2;
        float4 v0 = p4[0], v1 = p4[1];
        chunk[tid] = (v0.x+v0.y+v0.z+v0.w) + (v1.x+v1.y+v1.z+v1.w);
    }
    __syncthreads();
    if (tid < 32) {      // suffix scan of 256 chunks
        float loc[8];
        float run = 0.f;
        #pragma unroll
        for (int i = 7; i >= 0; i--) { run += chunk[tid*8 + i]; loc[i] = run; }
        float t_l = run, suf = run;
        #pragma unroll
        for (int off = 1; off < 32; off <<= 1) {
            float v = __shfl_down_sync(FULL, suf, off);
            if (tid + off < 32) suf += v;
        }
        float above = suf - t_l;
        #pragma unroll
        for (int i = 0; i < 8; i++) csuf[tid*8 + i] = loc[i] + above;
        if (tid == 0) csuf[256] = 0.f;
    }
    __syncthreads();

    // σ taps into registers -- B-scope only (loaded after phase A's reg peak)
    const float4* tb4 = reinterpret_cast<const float4*>(tab);
    const float4  tr0 = tb4[lane];

    const float4* nb4 = reinterpret_cast<const float4*>(nbuf);
    float* gT = g_T + ct*257;
    int m = warp;
    for (; m + 16 <= 256; m += 32) {
        const float4* baseA = nb4 + m*2;          // window [8m-64, 8m+64) at padded offset 8m
        const float4* baseB = nb4 + (m+16)*2;
        float4 a0 = baseA[lane];
        float4 b0 = baseB[lane];
        float accA = a0.x*tr0.x + a0.y*tr0.y + a0.z*tr0.z + a0.w*tr0.w;
        float accB = b0.x*tr0.x + b0.y*tr0.y + b0.z*tr0.z + b0.w*tr0.w;
        #pragma unroll
        for (int off = 16; off; off >>= 1) {
            accA += __shfl_down_sync(FULL, accA, off);
            accB += __shfl_down_sync(FULL, accB, off);
        }
        if (lane == 0) {
            int ca = m + 8, cb = m + 24;
            float SA = (ca < 256) ? csuf[ca] : 0.f;
            float SB = (cb < 256) ? csuf[cb] : 0.f;
            atomicAdd(&gT[m],      SA + accA);
            atomicAdd(&gT[m + 16], SB + accB);
        }
    }
    if (m <= 256) {                                // warp 0 tail: m = 256
        const float4* base = nb4 + m*2;
        float4 a0 = base[lane];
        float acc = a0.x*tr0.x + a0.y*tr0.y + a0.z*tr0.z + a0.w*tr0.w;
        #pragma unroll
        for (int off = 16; off; off >>= 1)
            acc += __shfl_down_sync(FULL, acc, off);
        if (lane == 0) atomicAdd(&gT[m], acc);     // suffix is 0 for m=256
    }

    // ================= Ticket: last CTA of the whole grid does the reduction =================
    __syncthreads();
    if (tid == 0) {                 // barrier ordered all CTA writes; one fence suffices
        __threadfence();
        s_ticket = atomicAdd(&g_done_all, 1);
    }
    __syncthreads();
    if (s_ticket != NCTA - 1) return;
    if (tid == 0) atomicExch(&g_done_all, 0);   // self-reset for next replay

    // ================= Phase C: CDF L1 reduction =================
    float s = 0.f;
    for (int e = tid; e < NCH*256; e += 512) {
        int p  = e >> 8;
        int bb = e & 255;
        const float* Tp = g_T + p*257;
        const float* Tt = g_T + (NCH + p)*257;
        float p0 = __ldcg(&Tp[0]), t0 = __ldcg(&Tt[0]);
        float pe = __ldcg(&Tp[256]), te = __ldcg(&Tt[256]);
        float invp = 1.f / (p0 - pe);
        float invt = 1.f / (t0 - te);
        float cp  = (p0 - __ldcg(&Tp[bb+1])) * invp;
        float ctv = (t0 - __ldcg(&Tt[bb+1])) * invt;
        s += fabsf(cp - ctv);
    }
    #pragma unroll
    for (int off = 16; off; off >>= 1) s += __shfl_down_sync(FULL, s, off);
    if (lane == 0) s_red[warp] = s;
    __syncthreads();
    if (tid < 32) {
        float v = (tid < 16) ? s_red[tid] : 0.f;
        #pragma unroll
        for (int off = 16; off; off >>= 1) v += __shfl_down_sync(FULL, v, off);
        if (tid == 0) out[0] = v * (1.0f / (48.0f * 256.0f));
    }
    __syncthreads();
    // zero g_T for the next graph replay (values already consumed above)
    for (int i = tid; i < NCT*257; i += 512) g_T[i] = 0.f;
}

extern "C" void kernel_launch(void* const* d_in, const int* in_sizes, int n_in,
                              void* d_out, int out_size) {
    const float* pred = (const float*)d_in[0];
    const float* tgt  = (const float*)d_in[1];
    float* out = (float*)d_out;

    cudaFuncSetAttribute(k_all, cudaFuncAttributeMaxDynamicSharedMemorySize, K1_SMEM);
    k_all<<<dim3(NCT, NSLICE), 512, K1_SMEM>>>(pred, tgt, out);
}